// round 3
// baseline (speedup 1.0000x reference)
#include <cuda_runtime.h>

// Problem constants (fixed by the reference setup_inputs)
#define BB 8
#define CC 512
#define RR 128
#define HW (128 * 128)
#define NPLANE (BB * CC)

// Scratch (no allocations allowed in kernel_launch)
__device__ float g_sums[NPLANE];
__device__ float g_bias[NPLANE];
__device__ int   g_cnt[BB];      // zero-init; self-resetting per replay

// ---------------------------------------------------------------------------
// Kernel 1 (per batch): plane sums for batch b, plus last-CTA epilogue that
// computes y1 = relu6(w_guide @ y) and bias = relu6(BN(w_fuse @ y1)).
// Grid = 512 CTAs (one per channel), 256 threads.
// ---------------------------------------------------------------------------
__global__ __launch_bounds__(256) void reduce_batch_kernel(
    const float* __restrict__ x,
    const float* __restrict__ w_guide,   // [R, C] row-major
    const float* __restrict__ w_fuse,    // [C, R] row-major
    const float* __restrict__ bn_gamma,
    const float* __restrict__ bn_beta,
    const float* __restrict__ bn_mean,
    const float* __restrict__ bn_var,
    int b) {
    const int c     = blockIdx.x;
    const int plane = b * CC + c;
    const int tid   = threadIdx.x;
    const int wid   = tid >> 5;
    const int lane  = tid & 31;

    // ---- plane sum (loads batch b into L2 as a side effect) ----
    const float4* __restrict__ p =
        reinterpret_cast<const float4*>(x + (size_t)plane * HW);
    float s = 0.0f;
#pragma unroll
    for (int i = 0; i < HW / 4 / 256; ++i) {
        float4 v = p[tid + i * 256];
        s += (v.x + v.y) + (v.z + v.w);
    }
#pragma unroll
    for (int o = 16; o > 0; o >>= 1)
        s += __shfl_xor_sync(0xffffffffu, s, o);

    __shared__ float ws[8];
    if (lane == 0) ws[wid] = s;
    __syncthreads();
    if (tid < 8) {
        float t = ws[tid];
#pragma unroll
        for (int o = 4; o > 0; o >>= 1)
            t += __shfl_xor_sync(0x000000ffu, t, o);
        if (tid == 0) g_sums[plane] = t;
    }

    // ---- last-CTA-of-batch epilogue ----
    __shared__ int isLast;
    if (tid == 0) {
        __threadfence();
        isLast = (atomicAdd(&g_cnt[b], 1) == CC - 1) ? 1 : 0;
    }
    __syncthreads();
    if (!isLast) return;

    __shared__ float ysh[CC];
    __shared__ float y1sh[RR];

    for (int i = tid; i < CC; i += 256)
        ysh[i] = g_sums[b * CC + i] * (1.0f / (float)HW);
    __syncthreads();

    // y1[r] = relu6(dot(w_guide[r,:], y)); 8 warps, 16 outputs each
#pragma unroll
    for (int k = 0; k < RR / 8; ++k) {
        const int r = wid + 8 * k;
        const float4* __restrict__ row =
            reinterpret_cast<const float4*>(w_guide + (size_t)r * CC);
        float acc = 0.0f;
#pragma unroll
        for (int j = 0; j < 4; ++j) {
            float4 w = row[lane + 32 * j];
            const float* yy = &ysh[4 * (lane + 32 * j)];
            acc = fmaf(w.x, yy[0], acc);
            acc = fmaf(w.y, yy[1], acc);
            acc = fmaf(w.z, yy[2], acc);
            acc = fmaf(w.w, yy[3], acc);
        }
#pragma unroll
        for (int o = 16; o > 0; o >>= 1)
            acc += __shfl_xor_sync(0xffffffffu, acc, o);
        if (lane == 0) y1sh[r] = fminf(fmaxf(acc, 0.0f), 6.0f);
    }
    __syncthreads();

    // bias[c2] = relu6(BN(dot(w_fuse[c2,:], y1))); 8 warps, 64 outputs each
#pragma unroll
    for (int k = 0; k < CC / 8; ++k) {
        const int c2 = wid + 8 * k;
        const float4* __restrict__ row =
            reinterpret_cast<const float4*>(w_fuse + (size_t)c2 * RR);
        float4 w = row[lane];
        const float* yy = &y1sh[4 * lane];
        float acc = w.x * yy[0];
        acc = fmaf(w.y, yy[1], acc);
        acc = fmaf(w.z, yy[2], acc);
        acc = fmaf(w.w, yy[3], acc);
#pragma unroll
        for (int o = 16; o > 0; o >>= 1)
            acc += __shfl_xor_sync(0xffffffffu, acc, o);
        if (lane == 0) {
            const float inv_std = rsqrtf(bn_var[c2] + 1e-5f);
            float v = fmaf((acc - bn_mean[c2]) * inv_std, bn_gamma[c2], bn_beta[c2]);
            g_bias[b * CC + c2] = fminf(fmaxf(v, 0.0f), 6.0f);
        }
    }

    if (tid == 0) g_cnt[b] = 0;   // self-reset for next graph replay
}

// ---------------------------------------------------------------------------
// Kernel 2 (per batch): out = x + bias[plane]. Batch b's x is L2-resident
// from reduce_batch_kernel. __ldcs on reads (dead data after this), __stcs
// on writes (don't pollute L2 for the next batch).
// ---------------------------------------------------------------------------
__global__ __launch_bounds__(256) void add_batch_kernel(
    const float* __restrict__ x, float* __restrict__ out, int b) {
    const int plane = b * CC + blockIdx.x;
    const float bias = g_bias[plane];
    const float4* __restrict__ p =
        reinterpret_cast<const float4*>(x + (size_t)plane * HW);
    float4* __restrict__ o =
        reinterpret_cast<float4*>(out + (size_t)plane * HW);
    const int tid = threadIdx.x;

#pragma unroll
    for (int i = 0; i < HW / 4 / 256; ++i) {
        float4 v = __ldcs(&p[tid + i * 256]);
        v.x += bias; v.y += bias; v.z += bias; v.w += bias;
        __stcs(&o[tid + i * 256], v);
    }
}

extern "C" void kernel_launch(void* const* d_in, const int* in_sizes, int n_in,
                              void* d_out, int out_size) {
    const float* x        = (const float*)d_in[0];
    const float* w_guide  = (const float*)d_in[1];
    const float* w_fuse   = (const float*)d_in[2];
    const float* bn_gamma = (const float*)d_in[3];
    const float* bn_beta  = (const float*)d_in[4];
    const float* bn_mean  = (const float*)d_in[5];
    const float* bn_var   = (const float*)d_in[6];
    float* out = (float*)d_out;

    for (int b = 0; b < BB; ++b) {
        reduce_batch_kernel<<<CC, 256>>>(x, w_guide, w_fuse, bn_gamma, bn_beta,
                                         bn_mean, bn_var, b);
        add_batch_kernel<<<CC, 256>>>(x, out, b);
    }
}

// round 4
// speedup vs baseline: 1.1074x; 1.1074x over previous
#include <cuda_runtime.h>

// Problem constants (fixed by the reference setup_inputs)
#define BB 8
#define CC 512
#define RR 128
#define HW (128 * 128)
#define NPLANE (BB * CC)
#define HALFV (HW / 8)            // float4 elements per half-plane (2048)

// Scratch (no allocations allowed in kernel_launch)
__device__ float g_part[NPLANE * 2];   // half-plane partial sums
__device__ float g_bias[NPLANE];
__device__ int   g_cnt[BB];            // zero-init; self-resetting per replay

// ---------------------------------------------------------------------------
// Unified phase kernel.
//   bid <  nAdd : ADD half-plane of batch (p-1): out = x + bias  (L2 hits)
//   bid >= nAdd : REDUCE half-plane of batch p; last CTA of the 1024 computes
//                 bias(p) = relu6(BN(w_fuse @ relu6(w_guide @ mean(x)))).
// Each half-plane = 2048 float4 = 8 float4 per thread (256 threads).
// ---------------------------------------------------------------------------
__global__ __launch_bounds__(256) void phase_kernel(
    const float* __restrict__ x,
    float* __restrict__ out,
    const float* __restrict__ w_guide,   // [R, C] row-major
    const float* __restrict__ w_fuse,    // [C, R] row-major
    const float* __restrict__ bn_gamma,
    const float* __restrict__ bn_beta,
    const float* __restrict__ bn_mean,
    const float* __restrict__ bn_var,
    int p, int nAdd) {
    const int bid  = blockIdx.x;
    const int tid  = threadIdx.x;
    const int wid  = tid >> 5;
    const int lane = tid & 31;

    if (bid < nAdd) {
        // ---------------- ADD for batch p-1 (reads should be L2-resident) ---
        const int plane = (p - 1) * CC + (bid >> 1);
        const int half  = bid & 1;
        const float bias = g_bias[plane];
        const float4* __restrict__ src =
            reinterpret_cast<const float4*>(x + (size_t)plane * HW) + half * HALFV;
        float4* __restrict__ dst =
            reinterpret_cast<float4*>(out + (size_t)plane * HW) + half * HALFV;
#pragma unroll
        for (int i = 0; i < HALFV / 256; ++i) {
            float4 v = __ldcs(&src[tid + i * 256]);
            v.x += bias; v.y += bias; v.z += bias; v.w += bias;
            __stcs(&dst[tid + i * 256], v);
        }
        return;
    }

    // -------------------- REDUCE for batch p (allocates batch p in L2) -----
    const int rid   = bid - nAdd;
    const int c     = rid >> 1;
    const int half  = rid & 1;
    const int plane = p * CC + c;
    const float4* __restrict__ src =
        reinterpret_cast<const float4*>(x + (size_t)plane * HW) + half * HALFV;

    float s = 0.0f;
#pragma unroll
    for (int i = 0; i < HALFV / 256; ++i) {
        float4 v = src[tid + i * 256];
        s += (v.x + v.y) + (v.z + v.w);
    }
#pragma unroll
    for (int o = 16; o > 0; o >>= 1)
        s += __shfl_xor_sync(0xffffffffu, s, o);

    __shared__ float ws[8];
    if (lane == 0) ws[wid] = s;
    __syncthreads();
    if (tid < 8) {
        float t = ws[tid];
#pragma unroll
        for (int o = 4; o > 0; o >>= 1)
            t += __shfl_xor_sync(0x000000ffu, t, o);
        if (tid == 0) g_part[plane * 2 + half] = t;
    }

    // ---- last-CTA-of-batch epilogue: compute bias(p) ----
    __shared__ int isLast;
    if (tid == 0) {
        __threadfence();
        isLast = (atomicAdd(&g_cnt[p], 1) == 2 * CC - 1) ? 1 : 0;
    }
    __syncthreads();
    if (!isLast) return;
    if (tid == 0) __threadfence();   // acquire side
    __syncthreads();

    __shared__ float ysh[CC];
    __shared__ float y1sh[RR];

    for (int i = tid; i < CC; i += 256) {
        const int pl2 = (p * CC + i) * 2;
        ysh[i] = (g_part[pl2] + g_part[pl2 + 1]) * (1.0f / (float)HW);
    }
    __syncthreads();

    // y1[r] = relu6(dot(w_guide[r,:], y)); 8 warps x 16 outputs
#pragma unroll
    for (int k = 0; k < RR / 8; ++k) {
        const int r = wid + 8 * k;
        const float4* __restrict__ row =
            reinterpret_cast<const float4*>(w_guide + (size_t)r * CC);
        float acc = 0.0f;
#pragma unroll
        for (int j = 0; j < 4; ++j) {
            float4 w = row[lane + 32 * j];
            const float* yy = &ysh[4 * (lane + 32 * j)];
            acc = fmaf(w.x, yy[0], acc);
            acc = fmaf(w.y, yy[1], acc);
            acc = fmaf(w.z, yy[2], acc);
            acc = fmaf(w.w, yy[3], acc);
        }
#pragma unroll
        for (int o = 16; o > 0; o >>= 1)
            acc += __shfl_xor_sync(0xffffffffu, acc, o);
        if (lane == 0) y1sh[r] = fminf(fmaxf(acc, 0.0f), 6.0f);
    }
    __syncthreads();

    // bias[c2] = relu6(BN(dot(w_fuse[c2,:], y1))); 8 warps x 64 outputs
#pragma unroll
    for (int k = 0; k < CC / 8; ++k) {
        const int c2 = wid + 8 * k;
        const float4* __restrict__ row =
            reinterpret_cast<const float4*>(w_fuse + (size_t)c2 * RR);
        float4 w = row[lane];
        const float* yy = &y1sh[4 * lane];
        float acc = w.x * yy[0];
        acc = fmaf(w.y, yy[1], acc);
        acc = fmaf(w.z, yy[2], acc);
        acc = fmaf(w.w, yy[3], acc);
#pragma unroll
        for (int o = 16; o > 0; o >>= 1)
            acc += __shfl_xor_sync(0xffffffffu, acc, o);
        if (lane == 0) {
            const float inv_std = rsqrtf(bn_var[c2] + 1e-5f);
            float v = fmaf((acc - bn_mean[c2]) * inv_std, bn_gamma[c2], bn_beta[c2]);
            g_bias[p * CC + c2] = fminf(fmaxf(v, 0.0f), 6.0f);
        }
    }

    if (tid == 0) g_cnt[p] = 0;   // self-reset for next graph replay
}

extern "C" void kernel_launch(void* const* d_in, const int* in_sizes, int n_in,
                              void* d_out, int out_size) {
    const float* x        = (const float*)d_in[0];
    const float* w_guide  = (const float*)d_in[1];
    const float* w_fuse   = (const float*)d_in[2];
    const float* bn_gamma = (const float*)d_in[3];
    const float* bn_beta  = (const float*)d_in[4];
    const float* bn_mean  = (const float*)d_in[5];
    const float* bn_var   = (const float*)d_in[6];
    float* out = (float*)d_out;

    for (int p = 0; p <= BB; ++p) {
        const int nAdd = (p == 0) ? 0 : 2 * CC;
        const int nRed = (p == BB) ? 0 : 2 * CC;
        phase_kernel<<<nAdd + nRed, 256>>>(x, out, w_guide, w_fuse, bn_gamma,
                                           bn_beta, bn_mean, bn_var, p, nAdd);
    }
}

// round 5
// speedup vs baseline: 1.4529x; 1.3120x over previous
#include <cuda_runtime.h>

// Problem constants (fixed by the reference setup_inputs)
#define BB 8
#define CC 512
#define RR 128
#define HW (128 * 128)
#define NPLANE (BB * CC)

// Scratch (no allocations allowed in kernel_launch)
__device__ float g_sums[NPLANE];
__device__ float g_bias[NPLANE];

// ---------------------------------------------------------------------------
// Plane reduce body: one 256-thread CTA sums one 16384-float plane.
// 16 fully-coalesced float4 loads per thread. No fences, no atomics.
// ---------------------------------------------------------------------------
__device__ __forceinline__ void plane_reduce(const float* __restrict__ x,
                                             int plane, int tid) {
    const float4* __restrict__ p =
        reinterpret_cast<const float4*>(x + (size_t)plane * HW);
    float s = 0.0f;
#pragma unroll
    for (int i = 0; i < HW / 4 / 256; ++i) {
        float4 v = p[tid + i * 256];
        s += (v.x + v.y) + (v.z + v.w);
    }
#pragma unroll
    for (int o = 16; o > 0; o >>= 1)
        s += __shfl_xor_sync(0xffffffffu, s, o);

    __shared__ float ws[8];
    if ((tid & 31) == 0) ws[tid >> 5] = s;
    __syncthreads();
    if (tid < 8) {
        float t = ws[tid];
#pragma unroll
        for (int o = 4; o > 0; o >>= 1)
            t += __shfl_xor_sync(0x000000ffu, t, o);
        if (tid == 0) g_sums[plane] = t;
    }
}

// ---------------------------------------------------------------------------
// Plane add body: out = x + bias, streamed. Default loads (L2-resident if the
// reduce of this batch ran in the previous launch); evict-first stores.
// ---------------------------------------------------------------------------
__device__ __forceinline__ void plane_add(const float* __restrict__ x,
                                          float* __restrict__ out,
                                          int plane, int tid) {
    const float bias = g_bias[plane];
    const float4* __restrict__ p =
        reinterpret_cast<const float4*>(x + (size_t)plane * HW);
    float4* __restrict__ o =
        reinterpret_cast<float4*>(out + (size_t)plane * HW);
#pragma unroll
    for (int i = 0; i < HW / 4 / 256; ++i) {
        float4 v = p[tid + i * 256];
        v.x += bias; v.y += bias; v.z += bias; v.w += bias;
        __stcs(&o[tid + i * 256], v);
    }
}

// Kernel: reduce batch p (512 CTAs, one per channel).
__global__ __launch_bounds__(256) void red_kernel(const float* __restrict__ x,
                                                  int p) {
    plane_reduce(x, p * CC + blockIdx.x, threadIdx.x);
}

// Kernel: fused add(p-1) + reduce(p). 1024 CTAs, no intra-kernel deps.
__global__ __launch_bounds__(256) void fused_kernel(const float* __restrict__ x,
                                                    float* __restrict__ out,
                                                    int p) {
    const int bid = blockIdx.x;
    if (bid < CC)
        plane_add(x, out, (p - 1) * CC + bid, threadIdx.x);
    else
        plane_reduce(x, p * CC + (bid - CC), threadIdx.x);
}

// Kernel: add batch p only (512 CTAs).
__global__ __launch_bounds__(256) void add_kernel(const float* __restrict__ x,
                                                  float* __restrict__ out,
                                                  int p) {
    plane_add(x, out, p * CC + blockIdx.x, threadIdx.x);
}

// ---------------------------------------------------------------------------
// mid kernel: bias(b) = relu6(BN(w_fuse @ relu6(w_guide @ mean))) for one
// batch. 1 CTA x 512 threads, warp-cooperative coalesced dots (R2-proven).
// Cross-launch ordering guarantees g_sums visibility — no sync needed.
// ---------------------------------------------------------------------------
__global__ __launch_bounds__(512) void mid_kernel(
    const float* __restrict__ w_guide,   // [R, C] row-major
    const float* __restrict__ w_fuse,    // [C, R] row-major
    const float* __restrict__ bn_gamma,
    const float* __restrict__ bn_beta,
    const float* __restrict__ bn_mean,
    const float* __restrict__ bn_var,
    int b) {
    const int t    = threadIdx.x;
    const int wid  = t >> 5;             // 0..15
    const int lane = t & 31;

    __shared__ float y[CC];
    __shared__ float y1[RR];

    y[t] = g_sums[b * CC + t] * (1.0f / (float)HW);
    __syncthreads();

#pragma unroll
    for (int k = 0; k < RR / 16; ++k) {
        const int r = wid + 16 * k;
        const float4* __restrict__ row =
            reinterpret_cast<const float4*>(w_guide + (size_t)r * CC);
        float acc = 0.0f;
#pragma unroll
        for (int j = 0; j < 4; ++j) {
            float4 w = row[lane + 32 * j];
            const float* yy = &y[4 * (lane + 32 * j)];
            acc = fmaf(w.x, yy[0], acc);
            acc = fmaf(w.y, yy[1], acc);
            acc = fmaf(w.z, yy[2], acc);
            acc = fmaf(w.w, yy[3], acc);
        }
#pragma unroll
        for (int o = 16; o > 0; o >>= 1)
            acc += __shfl_xor_sync(0xffffffffu, acc, o);
        if (lane == 0) y1[r] = fminf(fmaxf(acc, 0.0f), 6.0f);
    }
    __syncthreads();

#pragma unroll
    for (int k = 0; k < CC / 16; ++k) {
        const int c = wid + 16 * k;
        const float4* __restrict__ row =
            reinterpret_cast<const float4*>(w_fuse + (size_t)c * RR);
        float4 w = row[lane];
        const float* yy = &y1[4 * lane];
        float acc = w.x * yy[0];
        acc = fmaf(w.y, yy[1], acc);
        acc = fmaf(w.z, yy[2], acc);
        acc = fmaf(w.w, yy[3], acc);
#pragma unroll
        for (int o = 16; o > 0; o >>= 1)
            acc += __shfl_xor_sync(0xffffffffu, acc, o);
        if (lane == 0) {
            const float inv_std = rsqrtf(bn_var[c] + 1e-5f);
            float v = fmaf((acc - bn_mean[c]) * inv_std, bn_gamma[c], bn_beta[c]);
            g_bias[b * CC + c] = fminf(fmaxf(v, 0.0f), 6.0f);
        }
    }
}

extern "C" void kernel_launch(void* const* d_in, const int* in_sizes, int n_in,
                              void* d_out, int out_size) {
    const float* x        = (const float*)d_in[0];
    const float* w_guide  = (const float*)d_in[1];
    const float* w_fuse   = (const float*)d_in[2];
    const float* bn_gamma = (const float*)d_in[3];
    const float* bn_beta  = (const float*)d_in[4];
    const float* bn_mean  = (const float*)d_in[5];
    const float* bn_var   = (const float*)d_in[6];
    float* out = (float*)d_out;

    // Pipeline: reduce(0) | mid(0) | [add(p-1) + reduce(p)] | mid(p) ... | add(7)
    red_kernel<<<CC, 256>>>(x, 0);
    mid_kernel<<<1, 512>>>(w_guide, w_fuse, bn_gamma, bn_beta, bn_mean, bn_var, 0);
    for (int p = 1; p < BB; ++p) {
        fused_kernel<<<2 * CC, 256>>>(x, out, p);
        mid_kernel<<<1, 512>>>(w_guide, w_fuse, bn_gamma, bn_beta, bn_mean,
                               bn_var, p);
    }
    add_kernel<<<CC, 256>>>(x, out, BB - 1);
}

// round 6
// speedup vs baseline: 2.7893x; 1.9198x over previous
#include <cuda_runtime.h>

// Problem constants (fixed by the reference setup_inputs)
#define BB 8
#define CC 512
#define RR 128
#define HW (128 * 128)
#define NPLANE (BB * CC)

// Scratch (no allocations allowed in kernel_launch)
__device__ float g_sums[NPLANE];          // per-plane sums
__device__ float g_y1[BB * RR];           // relu6(w_guide @ mean) per batch

// ---------------------------------------------------------------------------
// Plane reduce body: one 256-thread CTA sums one 16384-float plane.
// ---------------------------------------------------------------------------
__device__ __forceinline__ void plane_reduce(const float* __restrict__ x,
                                             int plane, int tid) {
    const float4* __restrict__ p =
        reinterpret_cast<const float4*>(x + (size_t)plane * HW);
    float s = 0.0f;
#pragma unroll
    for (int i = 0; i < HW / 4 / 256; ++i) {
        float4 v = p[tid + i * 256];
        s += (v.x + v.y) + (v.z + v.w);
    }
#pragma unroll
    for (int o = 16; o > 0; o >>= 1)
        s += __shfl_xor_sync(0xffffffffu, s, o);

    __shared__ float ws[8];
    if ((tid & 31) == 0) ws[tid >> 5] = s;
    __syncthreads();
    if (tid < 8) {
        float t = ws[tid];
#pragma unroll
        for (int o = 4; o > 0; o >>= 1)
            t += __shfl_xor_sync(0x000000ffu, t, o);
        if (tid == 0) g_sums[plane] = t;
    }
}

// ---------------------------------------------------------------------------
// Plane add body with INLINE bias: warp 0 computes
//   bias = relu6(BN(dot(w_fuse[c,:], y1[b])))   (128-length dot, 512B load)
// then all warps stream out = x + bias. x of this batch is L2-resident.
// ---------------------------------------------------------------------------
__device__ __forceinline__ void plane_add(
    const float* __restrict__ x, float* __restrict__ out,
    const float* __restrict__ w_fuse,
    const float* __restrict__ bn_gamma, const float* __restrict__ bn_beta,
    const float* __restrict__ bn_mean,  const float* __restrict__ bn_var,
    int b, int c, int tid) {
    __shared__ float bsh;
    const int wid  = tid >> 5;
    const int lane = tid & 31;

    if (wid == 0) {
        const float4* __restrict__ row =
            reinterpret_cast<const float4*>(w_fuse + (size_t)c * RR);
        const float4* __restrict__ y14 =
            reinterpret_cast<const float4*>(g_y1 + b * RR);
        float4 w = row[lane];
        float4 y = y14[lane];
        float acc = w.x * y.x;
        acc = fmaf(w.y, y.y, acc);
        acc = fmaf(w.z, y.z, acc);
        acc = fmaf(w.w, y.w, acc);
#pragma unroll
        for (int o = 16; o > 0; o >>= 1)
            acc += __shfl_xor_sync(0xffffffffu, acc, o);
        if (lane == 0) {
            const float inv_std = rsqrtf(bn_var[c] + 1e-5f);
            float v = fmaf((acc - bn_mean[c]) * inv_std, bn_gamma[c], bn_beta[c]);
            bsh = fminf(fmaxf(v, 0.0f), 6.0f);
        }
    }
    __syncthreads();
    const float bias = bsh;

    const int plane = b * CC + c;
    const float4* __restrict__ p =
        reinterpret_cast<const float4*>(x + (size_t)plane * HW);
    float4* __restrict__ o =
        reinterpret_cast<float4*>(out + (size_t)plane * HW);
#pragma unroll
    for (int i = 0; i < HW / 4 / 256; ++i) {
        float4 v = p[tid + i * 256];
        v.x += bias; v.y += bias; v.z += bias; v.w += bias;
        __stcs(&o[tid + i * 256], v);
    }
}

// Kernel: reduce batch p (512 CTAs, one per channel).
__global__ __launch_bounds__(256) void red_kernel(const float* __restrict__ x,
                                                  int p) {
    plane_reduce(x, p * CC + blockIdx.x, threadIdx.x);
}

// Kernel: fused add(p-1) + reduce(p). 1024 CTAs, no intra-kernel deps.
__global__ __launch_bounds__(256) void fused_kernel(
    const float* __restrict__ x, float* __restrict__ out,
    const float* __restrict__ w_fuse,
    const float* __restrict__ bn_gamma, const float* __restrict__ bn_beta,
    const float* __restrict__ bn_mean,  const float* __restrict__ bn_var,
    int p) {
    const int bid = blockIdx.x;
    if (bid < CC)
        plane_add(x, out, w_fuse, bn_gamma, bn_beta, bn_mean, bn_var,
                  p - 1, bid, threadIdx.x);
    else
        plane_reduce(x, p * CC + (bid - CC), threadIdx.x);
}

// Kernel: add batch p only (512 CTAs).
__global__ __launch_bounds__(256) void add_kernel(
    const float* __restrict__ x, float* __restrict__ out,
    const float* __restrict__ w_fuse,
    const float* __restrict__ bn_gamma, const float* __restrict__ bn_beta,
    const float* __restrict__ bn_mean,  const float* __restrict__ bn_var,
    int p) {
    plane_add(x, out, w_fuse, bn_gamma, bn_beta, bn_mean, bn_var,
              p, blockIdx.x, threadIdx.x);
}

// ---------------------------------------------------------------------------
// mid1 kernel: y1[b] = relu6((w_guide @ sums[b]) / HW).
// 16 CTAs x 8 warps, one warp per output row — parallel weight loads.
// ---------------------------------------------------------------------------
__global__ __launch_bounds__(256) void mid1_kernel(
    const float* __restrict__ w_guide,   // [R, C] row-major
    int b) {
    const int wid  = threadIdx.x >> 5;
    const int lane = threadIdx.x & 31;
    const int r    = blockIdx.x * 8 + wid;

    const float4* __restrict__ row =
        reinterpret_cast<const float4*>(w_guide + (size_t)r * CC);
    const float4* __restrict__ s4 =
        reinterpret_cast<const float4*>(g_sums + b * CC);

    float acc = 0.0f;
#pragma unroll
    for (int j = 0; j < 4; ++j) {
        float4 w = row[lane + 32 * j];
        float4 y = s4[lane + 32 * j];
        acc = fmaf(w.x, y.x, acc);
        acc = fmaf(w.y, y.y, acc);
        acc = fmaf(w.z, y.z, acc);
        acc = fmaf(w.w, y.w, acc);
    }
#pragma unroll
    for (int o = 16; o > 0; o >>= 1)
        acc += __shfl_xor_sync(0xffffffffu, acc, o);
    if (lane == 0) {
        float v = acc * (1.0f / (float)HW);
        g_y1[b * RR + r] = fminf(fmaxf(v, 0.0f), 6.0f);
    }
}

extern "C" void kernel_launch(void* const* d_in, const int* in_sizes, int n_in,
                              void* d_out, int out_size) {
    const float* x        = (const float*)d_in[0];
    const float* w_guide  = (const float*)d_in[1];
    const float* w_fuse   = (const float*)d_in[2];
    const float* bn_gamma = (const float*)d_in[3];
    const float* bn_beta  = (const float*)d_in[4];
    const float* bn_mean  = (const float*)d_in[5];
    const float* bn_var   = (const float*)d_in[6];
    float* out = (float*)d_out;

    // red(0) | mid1(0) | [add(p-1)+red(p) | mid1(p)] for p=1..7 | add(7)
    red_kernel<<<CC, 256>>>(x, 0);
    mid1_kernel<<<RR / 8, 256>>>(w_guide, 0);
    for (int p = 1; p < BB; ++p) {
        fused_kernel<<<2 * CC, 256>>>(x, out, w_fuse, bn_gamma, bn_beta,
                                      bn_mean, bn_var, p);
        mid1_kernel<<<RR / 8, 256>>>(w_guide, p);
    }
    add_kernel<<<CC, 256>>>(x, out, w_fuse, bn_gamma, bn_beta, bn_mean,
                            bn_var, BB - 1);
}

// round 7
// speedup vs baseline: 2.9949x; 1.0737x over previous
#include <cuda_runtime.h>

// Problem constants (fixed by the reference setup_inputs)
#define BB 8
#define CC 512
#define RR 128
#define HW (128 * 128)
#define NPLANE (BB * CC)

// Scratch (no allocations allowed in kernel_launch)
__device__ float g_sums[NPLANE];          // per-plane sums
__device__ float g_y1[BB * RR];           // relu6(w_guide @ mean) per batch

// ---------------------------------------------------------------------------
// Plane reduce body: one 256-thread CTA sums one 16384-float plane.
// ---------------------------------------------------------------------------
__device__ __forceinline__ void plane_reduce(const float* __restrict__ x,
                                             int plane, int tid) {
    const float4* __restrict__ p =
        reinterpret_cast<const float4*>(x + (size_t)plane * HW);
    float s = 0.0f;
#pragma unroll
    for (int i = 0; i < HW / 4 / 256; ++i) {
        float4 v = p[tid + i * 256];
        s += (v.x + v.y) + (v.z + v.w);
    }
#pragma unroll
    for (int o = 16; o > 0; o >>= 1)
        s += __shfl_xor_sync(0xffffffffu, s, o);

    __shared__ float ws[8];
    if ((tid & 31) == 0) ws[tid >> 5] = s;
    __syncthreads();
    if (tid < 8) {
        float t = ws[tid];
#pragma unroll
        for (int o = 4; o > 0; o >>= 1)
            t += __shfl_xor_sync(0x000000ffu, t, o);
        if (tid == 0) g_sums[plane] = t;
    }
}

// ---------------------------------------------------------------------------
// Plane add body with INLINE bias: warp 0 computes
//   bias = relu6(BN(dot(w_fuse[c,:], y1[b])))   (128-length dot, 512B load)
// then all warps stream out = x + bias. Reads __ldcs (dead after), stores
// __stcs (evict-first) — keep L2 free for the concurrent reduce stream.
// ---------------------------------------------------------------------------
__device__ __forceinline__ void plane_add(
    const float* __restrict__ x, float* __restrict__ out,
    const float* __restrict__ w_fuse,
    const float* __restrict__ bn_gamma, const float* __restrict__ bn_beta,
    const float* __restrict__ bn_mean,  const float* __restrict__ bn_var,
    int b, int c, int tid) {
    __shared__ float bsh;
    const int wid  = tid >> 5;
    const int lane = tid & 31;

    if (wid == 0) {
        const float4* __restrict__ row =
            reinterpret_cast<const float4*>(w_fuse + (size_t)c * RR);
        const float4* __restrict__ y14 =
            reinterpret_cast<const float4*>(g_y1 + b * RR);
        float4 w = row[lane];
        float4 y = y14[lane];
        float acc = w.x * y.x;
        acc = fmaf(w.y, y.y, acc);
        acc = fmaf(w.z, y.z, acc);
        acc = fmaf(w.w, y.w, acc);
#pragma unroll
        for (int o = 16; o > 0; o >>= 1)
            acc += __shfl_xor_sync(0xffffffffu, acc, o);
        if (lane == 0) {
            const float inv_std = rsqrtf(bn_var[c] + 1e-5f);
            float v = fmaf((acc - bn_mean[c]) * inv_std, bn_gamma[c], bn_beta[c]);
            bsh = fminf(fmaxf(v, 0.0f), 6.0f);
        }
    }
    __syncthreads();
    const float bias = bsh;

    const int plane = b * CC + c;
    const float4* __restrict__ p =
        reinterpret_cast<const float4*>(x + (size_t)plane * HW);
    float4* __restrict__ o =
        reinterpret_cast<float4*>(out + (size_t)plane * HW);
#pragma unroll
    for (int i = 0; i < HW / 4 / 256; ++i) {
        float4 v = __ldcs(&p[tid + i * 256]);
        v.x += bias; v.y += bias; v.z += bias; v.w += bias;
        __stcs(&o[tid + i * 256], v);
    }
}

// Kernel: reduce batches b0, b0+1 (1024 CTAs; planes contiguous in memory).
__global__ __launch_bounds__(256) void red2_kernel(const float* __restrict__ x,
                                                   int b0) {
    plane_reduce(x, b0 * CC + blockIdx.x, threadIdx.x);
}

// Kernel: fused add(b0-2, b0-1) + reduce(b0, b0+1). 2048 CTAs.
__global__ __launch_bounds__(256) void fused_kernel(
    const float* __restrict__ x, float* __restrict__ out,
    const float* __restrict__ w_fuse,
    const float* __restrict__ bn_gamma, const float* __restrict__ bn_beta,
    const float* __restrict__ bn_mean,  const float* __restrict__ bn_var,
    int b0) {
    const int bid = blockIdx.x;
    if (bid < 2 * CC) {
        const int plane = (b0 - 2) * CC + bid;     // batches b0-2, b0-1
        plane_add(x, out, w_fuse, bn_gamma, bn_beta, bn_mean, bn_var,
                  plane / CC, plane % CC, threadIdx.x);
    } else {
        plane_reduce(x, b0 * CC + (bid - 2 * CC), threadIdx.x);
    }
}

// Kernel: add batches b0, b0+1 only (1024 CTAs).
__global__ __launch_bounds__(256) void add2_kernel(
    const float* __restrict__ x, float* __restrict__ out,
    const float* __restrict__ w_fuse,
    const float* __restrict__ bn_gamma, const float* __restrict__ bn_beta,
    const float* __restrict__ bn_mean,  const float* __restrict__ bn_var,
    int b0) {
    const int plane = b0 * CC + blockIdx.x;
    plane_add(x, out, w_fuse, bn_gamma, bn_beta, bn_mean, bn_var,
              plane / CC, plane % CC, threadIdx.x);
}

// ---------------------------------------------------------------------------
// mid1 kernel: y1[b][r] = relu6((w_guide[r,:] @ sums[b]) / HW) for b=b0,b0+1.
// One CTA per output row r (128 CTAs x 128 threads): w_guide row loaded once,
// dotted with both batches' sums. High CTA count hides cold-DRAM latency.
// ---------------------------------------------------------------------------
__global__ __launch_bounds__(128) void mid1_kernel(
    const float* __restrict__ w_guide,   // [R, C] row-major
    int b0) {
    const int r    = blockIdx.x;
    const int t    = threadIdx.x;
    const int wid  = t >> 5;
    const int lane = t & 31;

    const float4* __restrict__ row =
        reinterpret_cast<const float4*>(w_guide + (size_t)r * CC);
    const float4* __restrict__ s0 =
        reinterpret_cast<const float4*>(g_sums + (size_t)b0 * CC);
    const float4* __restrict__ s1 =
        reinterpret_cast<const float4*>(g_sums + (size_t)(b0 + 1) * CC);

    float4 w = row[t];           // 128 threads x float4 = 512 floats
    float4 a = s0[t];
    float4 b = s1[t];
    float acc0 = w.x * a.x;
    acc0 = fmaf(w.y, a.y, acc0);
    acc0 = fmaf(w.z, a.z, acc0);
    acc0 = fmaf(w.w, a.w, acc0);
    float acc1 = w.x * b.x;
    acc1 = fmaf(w.y, b.y, acc1);
    acc1 = fmaf(w.z, b.z, acc1);
    acc1 = fmaf(w.w, b.w, acc1);

#pragma unroll
    for (int o = 16; o > 0; o >>= 1) {
        acc0 += __shfl_xor_sync(0xffffffffu, acc0, o);
        acc1 += __shfl_xor_sync(0xffffffffu, acc1, o);
    }

    __shared__ float sm0[4], sm1[4];
    if (lane == 0) { sm0[wid] = acc0; sm1[wid] = acc1; }
    __syncthreads();
    if (t == 0) {
        float v0 = (sm0[0] + sm0[1] + sm0[2] + sm0[3]) * (1.0f / (float)HW);
        float v1 = (sm1[0] + sm1[1] + sm1[2] + sm1[3]) * (1.0f / (float)HW);
        g_y1[b0 * RR + r]       = fminf(fmaxf(v0, 0.0f), 6.0f);
        g_y1[(b0 + 1) * RR + r] = fminf(fmaxf(v1, 0.0f), 6.0f);
    }
}

extern "C" void kernel_launch(void* const* d_in, const int* in_sizes, int n_in,
                              void* d_out, int out_size) {
    const float* x        = (const float*)d_in[0];
    const float* w_guide  = (const float*)d_in[1];
    const float* w_fuse   = (const float*)d_in[2];
    const float* bn_gamma = (const float*)d_in[3];
    const float* bn_beta  = (const float*)d_in[4];
    const float* bn_mean  = (const float*)d_in[5];
    const float* bn_var   = (const float*)d_in[6];
    float* out = (float*)d_out;

    // red(0,1) | mid1 | [add(b0-2,b0-1)+red(b0,b0+1) | mid1] | add(6,7)
    red2_kernel<<<2 * CC, 256>>>(x, 0);
    mid1_kernel<<<RR, 128>>>(w_guide, 0);
    for (int b0 = 2; b0 < BB; b0 += 2) {
        fused_kernel<<<4 * CC, 256>>>(x, out, w_fuse, bn_gamma, bn_beta,
                                      bn_mean, bn_var, b0);
        mid1_kernel<<<RR, 128>>>(w_guide, b0);
    }
    add2_kernel<<<2 * CC, 256>>>(x, out, w_fuse, bn_gamma, bn_beta,
                                 bn_mean, bn_var, BB - 2);
}